// round 1
// baseline (speedup 1.0000x reference)
#include <cuda_runtime.h>

#define NMODELS 128
#define SZ      256        // SZ_IN == SZ_OUT
#define BATCH   4096
#define NTILES  4
#define TILE_O  64         // outputs per CTA tile
#define CH      8          // samples per chunk

// dyn smem layout (floats): W tile 16384 | inputs CH*256=2048 | partials CH*64*9=4608
#define SMEM_FLOATS (SZ*TILE_O + CH*SZ + CH*TILE_O*9)
#define SMEM_BYTES  (SMEM_FLOATS * 4)

__device__ int g_count[NMODELS];
__device__ int g_bucket[NMODELS * BATCH];

__global__ void zero_counts_kernel() {
    if (threadIdx.x < NMODELS) g_count[threadIdx.x] = 0;
}

__global__ void scatter_kernel(const int* __restrict__ ids) {
    int b = blockIdx.x * blockDim.x + threadIdx.x;
    if (b < BATCH) {
        int m = ids[b];
        int p = atomicAdd(&g_count[m], 1);
        g_bucket[m * BATCH + p] = b;
    }
}

__global__ void __launch_bounds__(256, 2)
gemm_kernel(const float* __restrict__ inp,
            const float* __restrict__ wlut,
            const float* __restrict__ blut,
            float* __restrict__ out)
{
    extern __shared__ float smem[];
    float* w_s  = smem;                    // [i*64 + j], i-major, 16384 floats
    float* in_s = w_s + SZ * TILE_O;       // [s*256 + i], 2048 floats
    float* part = in_s + CH * SZ;          // [(s*64+o)*9 + gg], 4608 floats

    const int t    = threadIdx.x;
    const int m    = blockIdx.x >> 2;      // model id
    const int tile = blockIdx.x & 3;       // output tile
    const int o4   = t & 15;               // which group of 4 outputs
    const int g    = t >> 4;               // which 16-row i slice (0..15)
    const int warp = t >> 5;
    const int lane = t & 31;

    const int cnt = g_count[m];
    const int* bk = g_bucket + m * BATCH;
    if (cnt == 0) return;   // whole block uniform

    // ---- load W tile into smem: w_s[i*64 + j] = W[m][i][tile*64 + j] ----
    const float* wm = wlut + (size_t)m * SZ * SZ + tile * TILE_O;
    float4* w_s4 = (float4*)w_s;
    #pragma unroll
    for (int k = t; k < SZ * TILE_O / 4; k += 256) {
        int i  = k >> 4;        // 16 float4 per 64-wide row
        int j4 = k & 15;
        w_s4[k] = ((const float4*)(wm + (size_t)i * SZ))[j4];
    }
    __syncthreads();

    for (int s0 = 0; s0 < cnt; s0 += CH) {
        const int ns = min(CH, cnt - s0);

        // ---- load up to CH input rows (zero-pad missing) ----
        #pragma unroll
        for (int k = t; k < CH * SZ / 4; k += 256) {
            int s  = k >> 6;     // 64 float4 per 256-wide row
            int i4 = k & 63;
            float4 v = make_float4(0.f, 0.f, 0.f, 0.f);
            if (s < ns) v = ((const float4*)(inp + (size_t)bk[s0 + s] * SZ))[i4];
            ((float4*)in_s)[k] = v;
        }
        __syncthreads();

        // ---- compute: each thread does 16 i-rows x 4 outputs x CH samples ----
        float acc[CH][4];
        #pragma unroll
        for (int s = 0; s < CH; s++)
            #pragma unroll
            for (int c = 0; c < 4; c++) acc[s][c] = 0.f;

        const int ibase0 = g << 4;
        #pragma unroll
        for (int ii = 0; ii < 16; ii += 4) {
            const int ib = ibase0 + ii;
            float wreg[4][4];
            *(float4*)wreg[0] = *(const float4*)&w_s[(ib + 0) * TILE_O + (o4 << 2)];
            *(float4*)wreg[1] = *(const float4*)&w_s[(ib + 1) * TILE_O + (o4 << 2)];
            *(float4*)wreg[2] = *(const float4*)&w_s[(ib + 2) * TILE_O + (o4 << 2)];
            *(float4*)wreg[3] = *(const float4*)&w_s[(ib + 3) * TILE_O + (o4 << 2)];
            #pragma unroll
            for (int s = 0; s < CH; s++) {
                float x[4];
                *(float4*)x = *(const float4*)&in_s[s * SZ + ib];
                #pragma unroll
                for (int k = 0; k < 4; k++)
                    #pragma unroll
                    for (int c = 0; c < 4; c++)
                        acc[s][c] = fmaf(x[k], wreg[k][c], acc[s][c]);
            }
        }

        // ---- reduction: pair-combine g (same warp, lanes t and t+16), then smem ----
        #pragma unroll
        for (int s = 0; s < CH; s++) {
            #pragma unroll
            for (int c = 0; c < 4; c++) {
                float v = acc[s][c];
                v += __shfl_down_sync(0xffffffffu, v, 16);
                if (lane < 16) {
                    int o = (o4 << 2) + c;
                    part[(s * TILE_O + o) * 9 + warp] = v;
                }
            }
        }
        __syncthreads();

        // ---- final: sum 8 warp-partials + bias, write out ----
        #pragma unroll
        for (int p = t; p < CH * TILE_O; p += 256) {
            int s = p >> 6;
            int o = p & 63;
            if (s < ns) {
                float sum = blut[m * SZ + tile * TILE_O + o];
                #pragma unroll
                for (int gg = 0; gg < 8; gg++) sum += part[p * 9 + gg];
                out[(size_t)bk[s0 + s] * SZ + tile * TILE_O + o] = sum;
            }
        }
        __syncthreads();   // protect in_s/part before next chunk
    }
}

extern "C" void kernel_launch(void* const* d_in, const int* in_sizes, int n_in,
                              void* d_out, int out_size) {
    const float* inp  = (const float*)d_in[0];
    const int*   ids  = (const int*)  d_in[1];
    const float* wlut = (const float*)d_in[2];
    const float* blut = (const float*)d_in[3];
    float* out = (float*)d_out;

    cudaFuncSetAttribute(gemm_kernel,
                         cudaFuncAttributeMaxDynamicSharedMemorySize, SMEM_BYTES);

    zero_counts_kernel<<<1, 128>>>();
    scatter_kernel<<<BATCH / 256, 256>>>(ids);
    gemm_kernel<<<NMODELS * NTILES, 256, SMEM_BYTES>>>(inp, wlut, blut, out);
}

// round 2
// speedup vs baseline: 1.0513x; 1.0513x over previous
#include <cuda_runtime.h>

#define NMODELS 128
#define SZ      256        // SZ_IN == SZ_OUT
#define BATCH   4096
#define NTILES  4
#define TILE_O  64         // outputs per CTA tile
#define CH      8          // samples per chunk

// dyn smem (floats): W tile 16384 | inputs CH*256=2048 | partials CH*64*9=4608
// then bucket int[BATCH]
#define W_FLOATS    (SZ * TILE_O)
#define IN_FLOATS   (CH * SZ)
#define PART_FLOATS (CH * TILE_O * 9)
#define SMEM_BYTES  ((W_FLOATS + IN_FLOATS + PART_FLOATS) * 4 + BATCH * 4)

__global__ void __launch_bounds__(256, 2)
fused_kernel(const float* __restrict__ inp,
             const int*   __restrict__ ids,
             const float* __restrict__ wlut,
             const float* __restrict__ blut,
             float* __restrict__ out)
{
    extern __shared__ float smem[];
    float* w_s    = smem;                       // [i*64 + j], i-major
    float* in_s   = w_s  + W_FLOATS;            // [s*256 + i]
    float* part   = in_s + IN_FLOATS;           // [(s*64+o)*9 + warp]
    int*   bucket = (int*)(part + PART_FLOATS); // up to BATCH entries
    __shared__ int cnt_s;

    const int t    = threadIdx.x;
    const int m    = blockIdx.x >> 2;      // model id
    const int tile = blockIdx.x & 3;       // output tile
    const int o4   = t & 15;               // group of 4 outputs
    const int g    = t >> 4;               // 16-row i slice (0..15)
    const int warp = t >> 5;
    const int lane = t & 31;

    if (t == 0) cnt_s = 0;
    __syncthreads();

    // ---- scan agent_ids, build this model's bucket in smem ----
    #pragma unroll
    for (int b = t; b < BATCH; b += 256) {
        if (__ldg(&ids[b]) == m) {
            int p = atomicAdd(&cnt_s, 1);
            bucket[p] = b;
        }
    }

    // ---- load W tile into smem (overlaps scan's L2 latency) ----
    const float* wm = wlut + (size_t)m * SZ * SZ + tile * TILE_O;
    float4* w_s4 = (float4*)w_s;
    #pragma unroll
    for (int k = t; k < W_FLOATS / 4; k += 256) {
        int i  = k >> 4;        // 16 float4 per 64-wide row
        int j4 = k & 15;
        w_s4[k] = ((const float4*)(wm + (size_t)i * SZ))[j4];
    }
    __syncthreads();

    const int cnt = cnt_s;
    if (cnt == 0) return;

    for (int s0 = 0; s0 < cnt; s0 += CH) {
        const int ns = min(CH, cnt - s0);

        // ---- load up to CH input rows (zero-pad missing) ----
        #pragma unroll
        for (int k = t; k < IN_FLOATS / 4; k += 256) {
            int s  = k >> 6;     // 64 float4 per 256-wide row
            int i4 = k & 63;
            float4 v = make_float4(0.f, 0.f, 0.f, 0.f);
            if (s < ns) v = ((const float4*)(inp + (size_t)bucket[s0 + s] * SZ))[i4];
            ((float4*)in_s)[k] = v;
        }
        __syncthreads();

        // ---- compute: 16 i-rows x 4 outputs x CH samples per thread ----
        float acc[CH][4];
        #pragma unroll
        for (int s = 0; s < CH; s++)
            #pragma unroll
            for (int c = 0; c < 4; c++) acc[s][c] = 0.f;

        const int ibase0 = g << 4;
        #pragma unroll
        for (int ii = 0; ii < 16; ii += 4) {
            const int ib = ibase0 + ii;
            float wreg[4][4];
            *(float4*)wreg[0] = *(const float4*)&w_s[(ib + 0) * TILE_O + (o4 << 2)];
            *(float4*)wreg[1] = *(const float4*)&w_s[(ib + 1) * TILE_O + (o4 << 2)];
            *(float4*)wreg[2] = *(const float4*)&w_s[(ib + 2) * TILE_O + (o4 << 2)];
            *(float4*)wreg[3] = *(const float4*)&w_s[(ib + 3) * TILE_O + (o4 << 2)];
            #pragma unroll
            for (int s = 0; s < CH; s++) {
                float x[4];
                *(float4*)x = *(const float4*)&in_s[s * SZ + ib];
                #pragma unroll
                for (int k = 0; k < 4; k++)
                    #pragma unroll
                    for (int c = 0; c < 4; c++)
                        acc[s][c] = fmaf(x[k], wreg[k][c], acc[s][c]);
            }
        }

        // ---- reduction: shfl-combine g pairs (lanes t, t+16), then smem ----
        #pragma unroll
        for (int s = 0; s < CH; s++) {
            #pragma unroll
            for (int c = 0; c < 4; c++) {
                float v = acc[s][c];
                v += __shfl_down_sync(0xffffffffu, v, 16);
                if (lane < 16) {
                    int o = (o4 << 2) + c;
                    part[(s * TILE_O + o) * 9 + warp] = v;
                }
            }
        }
        __syncthreads();

        // ---- final: sum 8 warp-partials + bias, write out ----
        #pragma unroll
        for (int p = t; p < CH * TILE_O; p += 256) {
            int s = p >> 6;
            int o = p & 63;
            if (s < ns) {
                float sum = blut[m * SZ + tile * TILE_O + o];
                #pragma unroll
                for (int gg = 0; gg < 8; gg++) sum += part[p * 9 + gg];
                out[(size_t)bucket[s0 + s] * SZ + tile * TILE_O + o] = sum;
            }
        }
        __syncthreads();   // protect in_s/part before next chunk
    }
}

extern "C" void kernel_launch(void* const* d_in, const int* in_sizes, int n_in,
                              void* d_out, int out_size) {
    const float* inp  = (const float*)d_in[0];
    const int*   ids  = (const int*)  d_in[1];
    const float* wlut = (const float*)d_in[2];
    const float* blut = (const float*)d_in[3];
    float* out = (float*)d_out;

    cudaFuncSetAttribute(fused_kernel,
                         cudaFuncAttributeMaxDynamicSharedMemorySize, SMEM_BYTES);

    fused_kernel<<<NMODELS * NTILES, 256, SMEM_BYTES>>>(inp, ids, wlut, blut, out);
}